// round 1
// baseline (speedup 1.0000x reference)
#include <cuda_runtime.h>
#include <cstdint>
#include <cstddef>

#define H_DIM 1024
#define S_DIM 64
#define C_CAPS 512
#define M_DIM (C_CAPS * S_DIM)   // 32768

// Scratch for e = x @ W  (128 MB, static device global — allocation-free rule)
__device__ float g_e[(size_t)M_DIM * H_DIM];

// ---- packed fp32x2 helpers (Blackwell FFMA2 — ptxas won't auto-fuse) ----
#define FMA_F32X2(d, a, b, c) \
    asm("fma.rn.f32x2 %0, %1, %2, %3;" : "=l"(d) : "l"(a), "l"(b), "l"(c))
#define PACK2(out, lo, hi) \
    asm("mov.b64 %0, {%1, %2};" : "=l"(out) : "r"(lo), "r"(hi))
#define UNPACK2(lo, hi, in) \
    asm("mov.b64 {%0, %1}, %2;" : "=r"(lo), "=r"(hi) : "l"(in))

// ============================================================================
// GEMM: g_e[M, H] = A[M, H] @ B[H, H]   (fp32, FFMA2 microkernel)
// Tile 128x128, BK=16, 256 threads, 8x8 per thread (packed as 8x4 f32x2 accs)
// ============================================================================
__global__ __launch_bounds__(256) void gemm_f32x2_kernel(
    const float* __restrict__ A, const float* __restrict__ B)
{
    const int K = H_DIM, N = H_DIM;
    __shared__ float As[16][129];   // +1 pad: transposed A stores ~conflict-free
    __shared__ float Bs[16][128];

    int tid = threadIdx.x;
    int tx = tid & 15, ty = tid >> 4;
    int rowBase = blockIdx.y * 128;
    int colBase = blockIdx.x * 128;

    int aRow = tid >> 2;            // 0..63
    int aCol = (tid & 3) << 2;      // 0,4,8,12
    int bRow = tid >> 5;            // 0..7
    int bCol = (tid & 31) << 2;     // 0..124

    unsigned long long acc[8][4];
    #pragma unroll
    for (int i = 0; i < 8; ++i)
        #pragma unroll
        for (int j = 0; j < 4; ++j) acc[i][j] = 0ULL;

    for (int k0 = 0; k0 < K; k0 += 16) {
        #pragma unroll
        for (int it = 0; it < 2; ++it) {
            int r = aRow + it * 64;
            float4 v = *(const float4*)(A + (size_t)(rowBase + r) * K + k0 + aCol);
            As[aCol + 0][r] = v.x;
            As[aCol + 1][r] = v.y;
            As[aCol + 2][r] = v.z;
            As[aCol + 3][r] = v.w;
        }
        #pragma unroll
        for (int it = 0; it < 2; ++it) {
            int r = bRow + it * 8;
            *(float4*)(&Bs[r][bCol]) =
                *(const float4*)(B + (size_t)(k0 + r) * N + colBase + bCol);
        }
        __syncthreads();

        #pragma unroll
        for (int k = 0; k < 16; ++k) {
            float4 b0 = *(const float4*)(&Bs[k][tx * 8]);
            float4 b1 = *(const float4*)(&Bs[k][tx * 8 + 4]);
            unsigned long long bb[4];
            PACK2(bb[0], __float_as_uint(b0.x), __float_as_uint(b0.y));
            PACK2(bb[1], __float_as_uint(b0.z), __float_as_uint(b0.w));
            PACK2(bb[2], __float_as_uint(b1.x), __float_as_uint(b1.y));
            PACK2(bb[3], __float_as_uint(b1.z), __float_as_uint(b1.w));
            #pragma unroll
            for (int i = 0; i < 8; ++i) {
                unsigned int au = __float_as_uint(As[k][ty * 8 + i]);
                unsigned long long aa;
                PACK2(aa, au, au);
                #pragma unroll
                for (int j = 0; j < 4; ++j)
                    FMA_F32X2(acc[i][j], aa, bb[j], acc[i][j]);
            }
        }
        __syncthreads();
    }

    #pragma unroll
    for (int i = 0; i < 8; ++i) {
        float o[8];
        #pragma unroll
        for (int j = 0; j < 4; ++j) {
            unsigned int lo, hi;
            UNPACK2(lo, hi, acc[i][j]);
            o[j * 2]     = __uint_as_float(lo);
            o[j * 2 + 1] = __uint_as_float(hi);
        }
        float* dst = g_e + (size_t)(rowBase + ty * 8 + i) * N + colBase + tx * 8;
        *(float4*)(dst)     = make_float4(o[0], o[1], o[2], o[3]);
        *(float4*)(dst + 4) = make_float4(o[4], o[5], o[6], o[7]);
    }
}

// ============================================================================
// Routing: one CTA per capsule. 3 iterations; last iteration only needs d.
// Then out = sum_s d_s * x_s.
// ============================================================================
__global__ __launch_bounds__(256) void routing_kernel(
    const float* __restrict__ x, float* __restrict__ out)
{
    int cap = blockIdx.x;
    const float* ec = g_e + (size_t)cap * S_DIM * H_DIM;
    const float* xc = x   + (size_t)cap * S_DIM * H_DIM;

    __shared__ float  bsh[S_DIM];
    __shared__ float  dsh[S_DIM];
    __shared__ float4 csh[H_DIM / 4];
    __shared__ float  red[8];

    int tid  = threadIdx.x;
    int lane = tid & 31;
    int wid  = tid >> 5;

    if (tid < S_DIM) bsh[tid] = 0.0f;
    __syncthreads();

    for (int t = 0; t < 3; ++t) {
        // softmax over S=64 (warp 0, 2 elems/lane)
        if (wid == 0) {
            float b0 = bsh[lane], b1 = bsh[lane + 32];
            float m = fmaxf(b0, b1);
            #pragma unroll
            for (int o = 16; o > 0; o >>= 1)
                m = fmaxf(m, __shfl_xor_sync(0xffffffffu, m, o));
            float e0 = expf(b0 - m), e1 = expf(b1 - m);
            float s = e0 + e1;
            #pragma unroll
            for (int o = 16; o > 0; o >>= 1)
                s += __shfl_xor_sync(0xffffffffu, s, o);
            float inv = 1.0f / s;
            dsh[lane]      = e0 * inv;
            dsh[lane + 32] = e1 * inv;
        }
        __syncthreads();
        if (t == 2) break;   // last iteration: only d is needed downstream

        // c[h] = sum_s d_s * e[s][h]   (thread owns 4 h via float4)
        float4 acc = make_float4(0.f, 0.f, 0.f, 0.f);
        for (int s = 0; s < S_DIM; ++s) {
            float ds = dsh[s];
            float4 v = ((const float4*)(ec + (size_t)s * H_DIM))[tid];
            acc.x = fmaf(ds, v.x, acc.x);
            acc.y = fmaf(ds, v.y, acc.y);
            acc.z = fmaf(ds, v.z, acc.z);
            acc.w = fmaf(ds, v.w, acc.w);
        }
        // normalize c
        float ss = acc.x * acc.x + acc.y * acc.y + acc.z * acc.z + acc.w * acc.w;
        #pragma unroll
        for (int o = 16; o > 0; o >>= 1)
            ss += __shfl_xor_sync(0xffffffffu, ss, o);
        if (lane == 0) red[wid] = ss;
        __syncthreads();
        if (tid == 0) {
            float tot = 0.f;
            #pragma unroll
            for (int w = 0; w < 8; ++w) tot += red[w];
            red[0] = rsqrtf(tot + 1e-9f);
        }
        __syncthreads();
        float inv = red[0];
        csh[tid] = make_float4(acc.x * inv, acc.y * inv, acc.z * inv, acc.w * inv);
        __syncthreads();

        // b[s] = dot(e[s], c) / 100   (each warp handles 8 s-values)
        for (int g = 0; g < 8; ++g) {
            int s = wid * 8 + g;
            const float4* row = (const float4*)(ec + (size_t)s * H_DIM);
            float sum = 0.f;
            #pragma unroll
            for (int kk = 0; kk < 8; ++kk) {
                float4 v  = row[lane + kk * 32];
                float4 cv = csh[lane + kk * 32];
                sum = fmaf(v.x, cv.x, sum);
                sum = fmaf(v.y, cv.y, sum);
                sum = fmaf(v.z, cv.z, sum);
                sum = fmaf(v.w, cv.w, sum);
            }
            #pragma unroll
            for (int o = 16; o > 0; o >>= 1)
                sum += __shfl_xor_sync(0xffffffffu, sum, o);
            if (lane == 0) bsh[s] = sum * 0.01f;
        }
        __syncthreads();
    }

    // out[cap][h] = sum_s d_s * x[cap][s][h]
    float4 acc = make_float4(0.f, 0.f, 0.f, 0.f);
    for (int s = 0; s < S_DIM; ++s) {
        float ds = dsh[s];
        float4 v = ((const float4*)(xc + (size_t)s * H_DIM))[tid];
        acc.x = fmaf(ds, v.x, acc.x);
        acc.y = fmaf(ds, v.y, acc.y);
        acc.z = fmaf(ds, v.z, acc.z);
        acc.w = fmaf(ds, v.w, acc.w);
    }
    ((float4*)(out + (size_t)cap * H_DIM))[tid] = acc;
}

// ============================================================================
extern "C" void kernel_launch(void* const* d_in, const int* in_sizes, int n_in,
                              void* d_out, int out_size)
{
    const float* x = (const float*)d_in[0];   // [512, 64, 1024]
    const float* W = (const float*)d_in[1];   // [1024, 1024]
    float* out = (float*)d_out;               // [512, 1024]

    dim3 grid(H_DIM / 128, M_DIM / 128);      // (8, 256)
    gemm_f32x2_kernel<<<grid, 256>>>(x, W);
    routing_kernel<<<C_CAPS, 256>>>(x, out);
}